// round 14
// baseline (speedup 1.0000x reference)
#include <cuda_runtime.h>
#include <cstdint>

// ---------------------------------------------------------------------------
// CRSD block: 2-layer leaky reservoir RNN.  B=32, T=1024, D=R=1024, ALPHA=0.1
// v7: proven v5 barrier backbone. Changes: 8KB chunks (64 rows) with NBUF=6
// ring and lookahead-5 (wait_group 4) so chunk fill latency (~765cyc) is fully
// covered by ~1.1Kcyc of pipeline slack; per-CTA rotated chunk order retained.
// Two dummy launches prepended so ncu -s 5 -c 1 lands on scan_kernel.
// ---------------------------------------------------------------------------

#define B_DIM 32
#define T_DIM 1024
#define D_DIM 1024
#define TD_STRIDE (T_DIM * T_DIM)
#define GRID_CTAS 128
#define NTHR 256
#define CH 2048                        // chunk: 64 rows x 32 batch = 8KB
#define NBUF 6
#define NCHA 32                        // phase A chunks (16 x + 16 h)
#define NCHB 16                        // phase B chunks

typedef unsigned long long ull;

__device__ float g_buf[(size_t)T_DIM * D_DIM * B_DIM];  // [t][k][b]
__device__ float g_hT[D_DIM * B_DIM];                    // [k][b]
__device__ float g_rT[D_DIM * B_DIM];                    // [k][b]
__device__ unsigned g_bar_count = 0;
__device__ unsigned g_bar_epoch = 0;
__device__ int g_dummy;

// ---- packed fp32x2 helpers -------------------------------------------------
__device__ __forceinline__ ull pk2(float w) {
    ull r;
    asm("mov.b64 %0, {%1, %1};" : "=l"(r) : "f"(w));
    return r;
}
__device__ __forceinline__ void ffma2(ull& acc, ull a, ull w) {
    asm("fma.rn.f32x2 %0, %1, %2, %0;" : "+l"(acc) : "l"(a), "l"(w));
}

// ---- cp.async.cg (L2-sourced => coherent across SMs) ------------------------
__device__ __forceinline__ unsigned smem_u32(const void* p) {
    unsigned a;
    asm("{ .reg .u64 t; cvta.to.shared.u64 t, %1; cvt.u32.u64 %0, t; }"
        : "=r"(a) : "l"(p));
    return a;
}
#define CP_COMMIT_EMPTY() asm volatile("cp.async.commit_group;" ::: "memory")
#define CP_WAIT4()        asm volatile("cp.async.wait_group 4;" ::: "memory")

// copy one 8KB chunk (2048 floats) global->smem; 256 thr x 2 x 16B; 1 group
__device__ __forceinline__ void cp_chunk8(float* dst, const float* src, int tid) {
    unsigned sb = smem_u32(dst) + tid * 16;
    const float* gp = src + tid * 4;
    asm volatile("cp.async.cg.shared.global [%0], [%1], 16;"
                 :: "r"(sb), "l"(gp) : "memory");
    asm volatile("cp.async.cg.shared.global [%0], [%1], 16;"
                 :: "r"(sb + 4096), "l"(gp + 1024) : "memory");
    asm volatile("cp.async.commit_group;" ::: "memory");
}

// ---- grid-wide barrier (128 CTAs co-resident, 1/SM) -------------------------
__device__ __forceinline__ void grid_barrier(unsigned& epoch) {
    __syncthreads();
    if (threadIdx.x == 0) {
        unsigned next = epoch + 1u;
        __threadfence();
        unsigned old = atomicAdd(&g_bar_count, 1u);
        if (old == GRID_CTAS - 1u) {
            atomicExch(&g_bar_count, 0u);
            __threadfence();
            atomicExch(&g_bar_epoch, next);
        } else {
            while (*((volatile unsigned*)&g_bar_epoch) != next) { }
        }
        epoch = next;
    }
    __syncthreads();
}

__device__ __forceinline__ int inc6(int v) { return (v == 5) ? 0 : v + 1; }

// ---------------------------------------------------------------------------
// SMEM: WA[2048][16], WB[1024][8], RED[4096], Ps[256], Rs[256], ACT 6 x 8KB.
// Total = 57856 floats = 231,424 B.
// ---------------------------------------------------------------------------
#define SMEM_FLOATS (2048*16 + 1024*8 + 4096 + 256 + 256 + NBUF*CH)
#define SMEM_BYTES  (SMEM_FLOATS * 4)

__global__ void __launch_bounds__(NTHR, 1)
scan_kernel(const float* __restrict__ Wxh, const float* __restrict__ Whh,
            const float* __restrict__ Wrh, const float* __restrict__ Wxr,
            const float* __restrict__ Whr, int layer)
{
    extern __shared__ float sm[];
    float* WA  = sm;                        // 2048*16
    float* WB  = WA + 2048 * 16;            // 1024*8
    float* RED = WB + 1024 * 8;             // 4096
    float* Ps  = RED + 4096;                // 256
    float* Rs  = Ps + 256;                  // 256
    float* ACT = Rs + 256;                  // 6*2048

    const int tid  = threadIdx.x;
    const int cta  = blockIdx.x;
    const int c8   = cta * 8;
    const int lane = tid & 31;
    const int warp = tid >> 5;
    const int rot  = cta & 15;              // rotation over 16 chunks per half

    const size_t DR = (size_t)D_DIM * D_DIM;
    const float* wxh = Wxh + (size_t)layer * DR;
    const float* whh = Whh + (size_t)layer * DR;
    const float* wrh = Wrh + (size_t)layer * DR;
    const float* wxr = Wxr + (size_t)layer * DR;
    const float* whr = Whr + (size_t)layer * DR;

    // ---- weight slices -> SMEM (once per layer) ----
    for (int i = tid; i < 8192; i += NTHR) {
        int k  = i >> 3;
        int jc = i & 7;
        int g  = k * D_DIM + c8 + jc;
        WA[k * 16 + jc]              = wxr[g];
        WA[k * 16 + 8 + jc]          = wxh[g];
        WA[(k + 1024) * 16 + jc]     = whr[g];
        WA[(k + 1024) * 16 + 8 + jc] = whh[g];
        WB[k * 8 + jc]               = wrh[g];
    }
    // ---- zero state ----
    {
        Rs[tid] = 0.0f;
        int j = tid >> 5, b = tid & 31;
        g_hT[(c8 + j) * 32 + b] = 0.0f;
    }
    unsigned epoch = *((volatile unsigned*)&g_bar_epoch);
    __threadfence();
    grid_barrier(epoch);

    const int jj = lane >> 2;   // 0..7
    const int bb = lane & 3;    // 0..3

    // rotated chunk maps (within each 16-chunk half)
    auto ciA = [&](int c) -> int {
        return (c < 16) ? ((c + rot) & 15) : (16 + ((c + rot) & 15));
    };
    auto ciB = [&](int c) -> int { return (c + rot) & 15; };

    int ibuf = 0, cbuf = 0;

    // ---- t=0 phase-A prologue: chunks A0..A4 (all x-half) ----
    #pragma unroll
    for (int p = 0; p < 5; ++p) {
        cp_chunk8(ACT + ibuf * CH, g_buf + ciA(p) * CH, tid);
        ibuf = inc6(ibuf);
    }

    for (int t = 0; t < T_DIM; ++t) {
        const float* xsrc = g_buf + (size_t)t * (D_DIM * B_DIM);

        // ================= PHASE A =================
        // U[32,16] = [x_t ; h](32x2048) @ WA(2048x16); 32 chunks of 64 rows.
        {
            ull acc[8];
            #pragma unroll
            for (int i = 0; i < 8; ++i) acc[i] = 0ULL;

            #pragma unroll 1
            for (int c = 0; c < NCHA; ++c) {
                CP_WAIT4();                 // chunk c's group complete
                __syncthreads();

                int nc = c + 5;
                if (nc < NCHA) {
                    int cin = ciA(nc);
                    const float* src = (cin < 16)
                        ? (xsrc + cin * CH)
                        : (g_hT + (cin - 16) * CH);
                    cp_chunk8(ACT + ibuf * CH, src, tid);
                    ibuf = inc6(ibuf);
                } else {
                    CP_COMMIT_EMPTY();
                }

                int ci = ciA(c);
                const float* cb   = ACT + cbuf * CH;
                cbuf = inc6(cbuf);
                const float* arow = cb + warp * (8 * 32) + bb * 8;
                const float* wrow = WA + (ci * 64 + warp * 8) * 16;

                #pragma unroll
                for (int kl = 0; kl < 8; ++kl) {
                    ulonglong2 a01 = *(const ulonglong2*)(arow + kl * 32);
                    ulonglong2 a23 = *(const ulonglong2*)(arow + kl * 32 + 4);
                    ull wp0 = pk2(wrow[kl * 16 + jj]);
                    ull wp1 = pk2(wrow[kl * 16 + 8 + jj]);
                    ffma2(acc[0], a01.x, wp0);
                    ffma2(acc[1], a01.y, wp0);
                    ffma2(acc[2], a23.x, wp0);
                    ffma2(acc[3], a23.y, wp0);
                    ffma2(acc[4], a01.x, wp1);
                    ffma2(acc[5], a01.y, wp1);
                    ffma2(acc[6], a23.x, wp1);
                    ffma2(acc[7], a23.y, wp1);
                }
            }

            float* rw = RED + warp * 512;
            ull* p0 = (ull*)(rw + jj * 32 + bb * 8);
            p0[0] = acc[0]; p0[1] = acc[1]; p0[2] = acc[2]; p0[3] = acc[3];
            ull* p1 = (ull*)(rw + (jj + 8) * 32 + bb * 8);
            p1[0] = acc[4]; p1[1] = acc[5]; p1[2] = acc[6]; p1[3] = acc[7];
        }
        __syncthreads();
        // cross-warp reduce + r update / p stash
        #pragma unroll
        for (int o = tid; o < 512; o += NTHR) {
            float s = 0.0f;
            #pragma unroll
            for (int w = 0; w < 8; ++w) s += RED[w * 512 + o];
            int j = o >> 5, b = o & 31;
            if (j < 8) {
                float g  = tanhf(s);
                float rn = 0.9f * Rs[o] + 0.1f * g;
                Rs[o] = rn;
                g_rT[(c8 + j) * 32 + b] = rn;
            } else {
                Ps[o - 256] = s;
            }
        }
        __threadfence();
        grid_barrier(epoch);   // r_new globally visible

        // ================= PHASE B =================
        // Z[32,8] = r_new(32x1024) @ WB(1024x8); 16 chunks of 64 rows.
        {
            #pragma unroll
            for (int p = 0; p < 5; ++p) {
                cp_chunk8(ACT + ibuf * CH, g_rT + ciB(p) * CH, tid);
                ibuf = inc6(ibuf);
            }

            ull acc[4];
            #pragma unroll
            for (int i = 0; i < 4; ++i) acc[i] = 0ULL;

            #pragma unroll 1
            for (int c = 0; c < NCHB; ++c) {
                CP_WAIT4();
                __syncthreads();

                int nc = c + 5;
                if (nc < NCHB) {
                    cp_chunk8(ACT + ibuf * CH, g_rT + ciB(nc) * CH, tid);
                    ibuf = inc6(ibuf);
                } else if (t + 1 < T_DIM) {
                    // cross-step prefetch: next step's A chunks 0..4 (x-half)
                    const float* nx = g_buf + (size_t)(t + 1) * (D_DIM * B_DIM);
                    cp_chunk8(ACT + ibuf * CH, nx + ciA(nc - NCHB) * CH, tid);
                    ibuf = inc6(ibuf);
                } else {
                    CP_COMMIT_EMPTY();
                }

                int ci = ciB(c);
                const float* cb   = ACT + cbuf * CH;
                cbuf = inc6(cbuf);
                const float* arow = cb + warp * (8 * 32) + bb * 8;
                const float* wrow = WB + (ci * 64 + warp * 8) * 8;

                #pragma unroll
                for (int kl = 0; kl < 8; ++kl) {
                    ulonglong2 a01 = *(const ulonglong2*)(arow + kl * 32);
                    ulonglong2 a23 = *(const ulonglong2*)(arow + kl * 32 + 4);
                    ull wp = pk2(wrow[kl * 8 + jj]);
                    ffma2(acc[0], a01.x, wp);
                    ffma2(acc[1], a01.y, wp);
                    ffma2(acc[2], a23.x, wp);
                    ffma2(acc[3], a23.y, wp);
                }
            }

            float* rw = RED + warp * 256;
            ull* p0 = (ull*)(rw + jj * 32 + bb * 8);
            p0[0] = acc[0]; p0[1] = acc[1]; p0[2] = acc[2]; p0[3] = acc[3];
        }
        __syncthreads();
        {
            float z = 0.0f;
            #pragma unroll
            for (int w = 0; w < 8; ++w) z += RED[w * 256 + tid];
            int j = tid >> 5, b = tid & 31;
            float hn = tanhf(Ps[tid] + z);
            g_hT[(c8 + j) * 32 + b] = hn;
            g_buf[(size_t)t * (D_DIM * B_DIM) + (c8 + j) * 32 + b] = hn;
        }
        __threadfence();
        grid_barrier(epoch);   // h_new visible before next step
    }
}

// ---------------------------------------------------------------------------
// Dummy kernel (ncu launch-index alignment so -s 5 -c 1 lands on scan_kernel)
// ---------------------------------------------------------------------------
__global__ void dummy_k(int v) { if (threadIdx.x == 0) g_dummy = v; }

// ---------------------------------------------------------------------------
// Transposes: x[b][t][k]  <->  buf[t][k][b]
// ---------------------------------------------------------------------------
__global__ void transpose_in(const float* __restrict__ x)
{
    __shared__ float s[32][65];
    const int t  = blockIdx.y;
    const int k0 = blockIdx.x * 64;
    const int tid = threadIdx.x;

    #pragma unroll
    for (int p = 0; p < 8; ++p) {
        int b  = p * 4 + (tid >> 6);
        int kk = tid & 63;
        s[b][kk] = x[(size_t)b * TD_STRIDE + (size_t)t * D_DIM + k0 + kk];
    }
    __syncthreads();
    #pragma unroll
    for (int p = 0; p < 8; ++p) {
        int kk = p * 8 + (tid >> 5);
        int b  = tid & 31;
        g_buf[(size_t)t * (D_DIM * B_DIM) + (size_t)(k0 + kk) * 32 + b] = s[b][kk];
    }
}

__global__ void transpose_out(float* __restrict__ out)
{
    __shared__ float s[64][33];
    const int t  = blockIdx.y;
    const int j0 = blockIdx.x * 64;
    const int tid = threadIdx.x;

    #pragma unroll
    for (int p = 0; p < 8; ++p) {
        int jj = p * 8 + (tid >> 5);
        int b  = tid & 31;
        s[jj][b] = g_buf[(size_t)t * (D_DIM * B_DIM) + (size_t)(j0 + jj) * 32 + b];
    }
    __syncthreads();
    #pragma unroll
    for (int p = 0; p < 8; ++p) {
        int b  = p * 4 + (tid >> 6);
        int jc = tid & 63;
        out[(size_t)b * TD_STRIDE + (size_t)t * D_DIM + j0 + jc] = s[jc][b];
    }
}

// ---------------------------------------------------------------------------
extern "C" void kernel_launch(void* const* d_in, const int* in_sizes, int n_in,
                              void* d_out, int out_size)
{
    const float* x   = (const float*)d_in[0];
    const float* Wxh = (const float*)d_in[1];
    const float* Whh = (const float*)d_in[2];
    const float* Wrh = (const float*)d_in[3];
    const float* Wxr = (const float*)d_in[4];
    const float* Whr = (const float*)d_in[5];
    float* out = (float*)d_out;

    cudaFuncSetAttribute(scan_kernel,
                         cudaFuncAttributeMaxDynamicSharedMemorySize,
                         SMEM_BYTES);

    dummy_k<<<1, 32>>>(1);
    dummy_k<<<1, 32>>>(2);
    transpose_in<<<dim3(16, 1024), NTHR>>>(x);
    scan_kernel<<<GRID_CTAS, NTHR, SMEM_BYTES>>>(Wxh, Whh, Wrh, Wxr, Whr, 0);
    scan_kernel<<<GRID_CTAS, NTHR, SMEM_BYTES>>>(Wxh, Whh, Wrh, Wxr, Whr, 1);
    transpose_out<<<dim3(16, 1024), NTHR>>>(out);
}